// round 1
// baseline (speedup 1.0000x reference)
#include <cuda_runtime.h>
#include <cuda_bf16.h>
#include <math.h>

// ---------------- problem constants ----------------
#define BATCH   2
#define TSEQ    512
#define NTOK    1024      // BATCH*TSEQ
#define DMODEL  1024
#define NHEADS  8
#define DKEY    128
#define HK      1024      // NHEADS*DKEY
#define NSUB    128
#define TOPK    16
#define HD      128       // DMODEL/NHEADS

// ---------------- scratch (device globals; no allocation allowed) ----------------
__device__ __align__(128) float g_q[NTOK * HK];
__device__ __align__(128) float g_qkv[NTOK * 3 * DMODEL];
__device__ __align__(128) float g_peer[NTOK * HK];
__device__ __align__(128) float g_peer_proj[NTOK * DMODEL];
__device__ __align__(128) float g_att[BATCH * NHEADS * TSEQ * TSEQ];   // 16 MB
__device__ __align__(128) float g_ao[NTOK * DMODEL];
__device__ __align__(128) float g_ao_proj[NTOK * DMODEL];

// ============================================================================
// Generic NT GEMM: C[M,N] = A[M,K] @ B[N,K]^T + bias[N]
// BM=128, BN=64, BK=16, 256 threads, 8x4 register tile.
// All dims must be multiples of the tile sizes (true for this problem).
// ============================================================================
__global__ void __launch_bounds__(256) gemm_nt_bias(
    const float* __restrict__ A, const float* __restrict__ B,
    const float* __restrict__ bias, float* __restrict__ C,
    int M, int N, int K)
{
    __shared__ float As[16][128];
    __shared__ float Bs[16][64];
    int t  = threadIdx.x;
    int m0 = blockIdx.y * 128;
    int n0 = blockIdx.x * 64;
    int tx = t & 15, ty = t >> 4;

    float acc[8][4];
#pragma unroll
    for (int i = 0; i < 8; i++)
#pragma unroll
        for (int j = 0; j < 4; j++) acc[i][j] = 0.f;

    for (int k0 = 0; k0 < K; k0 += 16) {
        // load A tile 128x16 (512 float4, 2 per thread), transposed into As[k][m]
#pragma unroll
        for (int s = 0; s < 2; s++) {
            int v = t + s * 256;
            int row = v >> 2, c4 = (v & 3) * 4;
            float4 a = *(const float4*)(A + (size_t)(m0 + row) * K + k0 + c4);
            As[c4 + 0][row] = a.x; As[c4 + 1][row] = a.y;
            As[c4 + 2][row] = a.z; As[c4 + 3][row] = a.w;
        }
        // load B tile 64x16 (256 float4, 1 per thread), transposed into Bs[k][n]
        {
            int row = t >> 2, c4 = (t & 3) * 4;
            float4 b = *(const float4*)(B + (size_t)(n0 + row) * K + k0 + c4);
            Bs[c4 + 0][row] = b.x; Bs[c4 + 1][row] = b.y;
            Bs[c4 + 2][row] = b.z; Bs[c4 + 3][row] = b.w;
        }
        __syncthreads();
#pragma unroll
        for (int kk = 0; kk < 16; kk++) {
            float ar[8], br[4];
#pragma unroll
            for (int i = 0; i < 8; i++) ar[i] = As[kk][ty * 8 + i];
#pragma unroll
            for (int j = 0; j < 4; j++) br[j] = Bs[kk][tx * 4 + j];
#pragma unroll
            for (int i = 0; i < 8; i++)
#pragma unroll
                for (int j = 0; j < 4; j++) acc[i][j] += ar[i] * br[j];
        }
        __syncthreads();
    }
#pragma unroll
    for (int i = 0; i < 8; i++) {
        int m = m0 + ty * 8 + i;
#pragma unroll
        for (int j = 0; j < 4; j++) {
            int n = n0 + tx * 4 + j;
            C[(size_t)m * N + n] = acc[i][j] + bias[n];
        }
    }
}

// ============================================================================
// PEER routing: BN(q) -> sub-key scores -> structured top-16 -> gather experts
// -> sim -> softmax -> weighted sum. One block per (token, head), 128 threads.
// Top-16 of {s1_i + s2_j} is a subset of top16(s1) x top16(s2); the final
// output is invariant to the ORDER of the selected set, so rank-select works.
// ============================================================================
__global__ void __launch_bounds__(128) peer_route(
    const float* __restrict__ bn_w, const float* __restrict__ bn_b,
    const float* __restrict__ bn_mean, const float* __restrict__ bn_var,
    const float* __restrict__ sub_keys, const float* __restrict__ expert_w)
{
    int token = blockIdx.x >> 3;
    int head  = blockIdx.x & 7;
    int tid   = threadIdx.x;

    __shared__ float q[128];
    __shared__ float s1[128], s2[128];
    __shared__ float v1[16], v2[16];
    __shared__ int   i1[16], i2[16];
    __shared__ float cval[256];
    __shared__ int   cidx[256];
    __shared__ int   sel[16];
    __shared__ float simv[16];
    __shared__ float rw[16];
    __shared__ float ews[16][128];

    int c = head * 128 + tid;
    float qraw = g_q[(size_t)token * HK + c];
    float qb = (qraw - bn_mean[c]) * rsqrtf(bn_var[c] + 1e-5f) * bn_w[c] + bn_b[c];
    q[tid] = qb;
    __syncthreads();

    // sub-key scores: s1 uses q[0:64], s2 uses q[64:128]
    float a1 = 0.f, a2 = 0.f;
    const float* k1p = sub_keys + (size_t)tid * 64;
    const float* k2p = sub_keys + (size_t)NSUB * 64 + (size_t)tid * 64;
#pragma unroll 8
    for (int i = 0; i < 64; i++) {
        a1 += q[i]      * k1p[i];
        a2 += q[64 + i] * k2p[i];
    }
    s1[tid] = a1; s2[tid] = a2;
    __syncthreads();

    // rank-based top-16 of s1 and s2 (total order via index tiebreak)
    int r1 = 0, r2 = 0;
    for (int j = 0; j < 128; j++) {
        float x1 = s1[j]; r1 += (x1 > a1) || (x1 == a1 && j < tid);
        float x2 = s2[j]; r2 += (x2 > a2) || (x2 == a2 && j < tid);
    }
    if (r1 < 16) { v1[r1] = a1; i1[r1] = tid; }
    if (r2 < 16) { v2[r2] = a2; i2[r2] = tid; }
    __syncthreads();

    // 256 candidate sums, rank-select top 16
    for (int p = tid; p < 256; p += 128) {
        int a = p >> 4, bb = p & 15;
        cval[p] = v1[a] + v2[bb];
        cidx[p] = i1[a] * NSUB + i2[bb];
    }
    __syncthreads();
    for (int p = tid; p < 256; p += 128) {
        float v = cval[p];
        int r = 0;
        for (int j = 0; j < 256; j++) {
            float w = cval[j];
            r += (w > v) || (w == v && j < p);
        }
        if (r < 16) sel[r] = cidx[p];
    }
    __syncthreads();

    // gather expert rows (coalesced per row)
#pragma unroll
    for (int k = 0; k < 16; k++)
        ews[k][tid] = expert_w[(size_t)sel[k] * DKEY + tid];
    __syncthreads();

    // sim_k = dot(q, ews[k]); 8 lanes per expert
    int k8 = tid >> 3, l8 = tid & 7;
    float part = 0.f;
#pragma unroll
    for (int i = 0; i < 16; i++) {
        int d = l8 * 16 + i;
        part += q[d] * ews[k8][d];
    }
    part += __shfl_down_sync(0xffffffffu, part, 4);
    part += __shfl_down_sync(0xffffffffu, part, 2);
    part += __shfl_down_sync(0xffffffffu, part, 1);
    if (l8 == 0) simv[k8] = part;
    __syncthreads();

    if (tid == 0) {
        float m = -INFINITY;
#pragma unroll
        for (int k = 0; k < 16; k++) m = fmaxf(m, simv[k]);
        float e[16]; float s = 0.f;
#pragma unroll
        for (int k = 0; k < 16; k++) { e[k] = expf(simv[k] - m); s += e[k]; }
        float inv = 1.f / s;
#pragma unroll
        for (int k = 0; k < 16; k++) rw[k] = e[k] * inv;
    }
    __syncthreads();

    float o = 0.f;
#pragma unroll
    for (int k = 0; k < 16; k++) o += rw[k] * ews[k][tid];
    g_peer[(size_t)token * HK + c] = o;
}

// ============================================================================
// Attention scores + softmax. Block = (16 q-rows, one (b,h)). 256 threads.
// Thread owns row r = t>>4 and keys k ≡ (t&15) (mod 16) within each 32-key
// tile → 32 score registers. Row softmax via 16-lane shfl group.
// ============================================================================
__global__ void __launch_bounds__(256) attn_scores()
{
    int z = blockIdx.y;          // b*8 + h
    int b = z >> 3, h = z & 7;
    int q0 = blockIdx.x * 16;
    int t = threadIdx.x;

    __shared__ float qs[16][128];
    __shared__ float Ks[32][129];

    // load q tile (16x128)
#pragma unroll
    for (int s = 0; s < 2; s++) {
        int v = t + s * 256;
        int r = v >> 5, c4 = (v & 31) * 4;
        float4 val = *(const float4*)&g_qkv[(size_t)(b * TSEQ + q0 + r) * (3 * DMODEL) + h * HD + c4];
        *(float4*)&qs[r][c4] = val;
    }
    __syncthreads();

    int j  = t & 15;
    int rr = t >> 4;
    float sreg[32];

    for (int kt = 0; kt < 16; kt++) {
        // load 32x128 K tile (transposed-padded rows)
#pragma unroll
        for (int s = 0; s < 4; s++) {
            int v = t + s * 256;
            int kr = v >> 5, c4 = (v & 31) * 4;
            float4 val = *(const float4*)&g_qkv[(size_t)(b * TSEQ + kt * 32 + kr) * (3 * DMODEL) + DMODEL + h * HD + c4];
            Ks[kr][c4 + 0] = val.x; Ks[kr][c4 + 1] = val.y;
            Ks[kr][c4 + 2] = val.z; Ks[kr][c4 + 3] = val.w;
        }
        __syncthreads();
        float acc1 = 0.f, acc2 = 0.f;
        int ka = j, kb = j + 16;
#pragma unroll 8
        for (int i = 0; i < 128; i++) {
            float qv = qs[rr][i];
            acc1 += qv * Ks[ka][i];
            acc2 += qv * Ks[kb][i];
        }
        sreg[2 * kt]     = acc1;
        sreg[2 * kt + 1] = acc2;
        __syncthreads();
    }

    const float scale = 0.08838834764831845f;  // 1/sqrt(128)
#pragma unroll
    for (int i = 0; i < 32; i++) sreg[i] *= scale;

    // row softmax over the 16 threads that share rr (they are 16 consecutive lanes)
    float m = -INFINITY;
#pragma unroll
    for (int i = 0; i < 32; i++) m = fmaxf(m, sreg[i]);
#pragma unroll
    for (int off = 8; off; off >>= 1)
        m = fmaxf(m, __shfl_xor_sync(0xffffffffu, m, off));
    float sum = 0.f;
#pragma unroll
    for (int i = 0; i < 32; i++) { sreg[i] = expf(sreg[i] - m); sum += sreg[i]; }
#pragma unroll
    for (int off = 8; off; off >>= 1)
        sum += __shfl_xor_sync(0xffffffffu, sum, off);
    float inv = 1.f / sum;

    float* arow = g_att + ((size_t)z * TSEQ + q0 + rr) * TSEQ;
#pragma unroll
    for (int kt = 0; kt < 16; kt++) {
        arow[kt * 32 + j]      = sreg[2 * kt] * inv;
        arow[kt * 32 + 16 + j] = sreg[2 * kt + 1] * inv;
    }
}

// ============================================================================
// AV GEMM (NN, strided): ao[b,q,h*128+e] = sum_k att[z,q,k] * V[b,k,h,e]
// BM=128, BN=64, BK=16. grid (128/64=2? -> N=128 so 2, M=512/128=4, z=16)
// ============================================================================
__global__ void __launch_bounds__(256) gemm_av()
{
    int z = blockIdx.z;
    int b = z >> 3, h = z & 7;
    const float* A  = g_att + (size_t)z * TSEQ * TSEQ;                       // lda=512
    const float* Bb = g_qkv + (size_t)b * TSEQ * (3 * DMODEL) + 2 * DMODEL + h * HD; // ldb=3072
    float* Cb = g_ao + (size_t)b * TSEQ * DMODEL + h * HD;                   // ldc=1024

    __shared__ float As[16][128];
    __shared__ float Bs[16][64];
    int t  = threadIdx.x;
    int m0 = blockIdx.y * 128;
    int n0 = blockIdx.x * 64;
    int tx = t & 15, ty = t >> 4;

    float acc[8][4];
#pragma unroll
    for (int i = 0; i < 8; i++)
#pragma unroll
        for (int j = 0; j < 4; j++) acc[i][j] = 0.f;

    for (int k0 = 0; k0 < TSEQ; k0 += 16) {
#pragma unroll
        for (int s = 0; s < 2; s++) {
            int v = t + s * 256;
            int row = v >> 2, c4 = (v & 3) * 4;
            float4 a = *(const float4*)(A + (size_t)(m0 + row) * TSEQ + k0 + c4);
            As[c4 + 0][row] = a.x; As[c4 + 1][row] = a.y;
            As[c4 + 2][row] = a.z; As[c4 + 3][row] = a.w;
        }
        {
            int kr = t >> 4, c4 = (t & 15) * 4;
            float4 bv = *(const float4*)(Bb + (size_t)(k0 + kr) * (3 * DMODEL) + n0 + c4);
            *(float4*)&Bs[kr][c4] = bv;
        }
        __syncthreads();
#pragma unroll
        for (int kk = 0; kk < 16; kk++) {
            float ar[8], br[4];
#pragma unroll
            for (int i = 0; i < 8; i++) ar[i] = As[kk][ty * 8 + i];
#pragma unroll
            for (int jj = 0; jj < 4; jj++) br[jj] = Bs[kk][tx * 4 + jj];
#pragma unroll
            for (int i = 0; i < 8; i++)
#pragma unroll
                for (int jj = 0; jj < 4; jj++) acc[i][jj] += ar[i] * br[jj];
        }
        __syncthreads();
    }
#pragma unroll
    for (int i = 0; i < 8; i++) {
        int m = m0 + ty * 8 + i;
#pragma unroll
        for (int jj = 0; jj < 4; jj++) {
            Cb[(size_t)m * DMODEL + n0 + tx * 4 + jj] = acc[i][jj];
        }
    }
}

// mean over heads for attn_weights output
__global__ void __launch_bounds__(256) attn_mean(float* __restrict__ out)
{
    int idx = blockIdx.x * 256 + threadIdx.x;     // 0 .. 524287
    int b   = idx / (TSEQ * TSEQ);
    int rem = idx - b * (TSEQ * TSEQ);
    float s = 0.f;
#pragma unroll
    for (int h = 0; h < 8; h++)
        s += g_att[((size_t)(b * 8 + h)) * (TSEQ * TSEQ) + rem];
    out[idx] = s * 0.125f;
}

// final: y = rmsnorm(x + peer_proj + ao_proj) * rms_w
__global__ void __launch_bounds__(256) final_rms(
    const float* __restrict__ x, const float* __restrict__ rms_w,
    float* __restrict__ y)
{
    int token = blockIdx.x;
    int t = threadIdx.x;
    size_t base = (size_t)token * DMODEL;
    float v[4];
    float ss = 0.f;
#pragma unroll
    for (int u = 0; u < 4; u++) {
        int c = t + u * 256;
        float s = x[base + c] + g_peer_proj[base + c] + g_ao_proj[base + c];
        v[u] = s;
        ss += s * s;
    }
#pragma unroll
    for (int off = 16; off; off >>= 1)
        ss += __shfl_xor_sync(0xffffffffu, ss, off);
    __shared__ float red[8];
    __shared__ float stot;
    if ((t & 31) == 0) red[t >> 5] = ss;
    __syncthreads();
    if (t == 0) {
        float s = 0.f;
#pragma unroll
        for (int i = 0; i < 8; i++) s += red[i];
        stot = rsqrtf(s * (1.f / DMODEL) + 1e-6f);
    }
    __syncthreads();
    float inv = stot;
#pragma unroll
    for (int u = 0; u < 4; u++) {
        int c = t + u * 256;
        y[base + c] = v[u] * inv * rms_w[c];
    }
}

// ============================================================================
extern "C" void kernel_launch(void* const* d_in, const int* in_sizes, int n_in,
                              void* d_out, int out_size)
{
    const float* x         = (const float*)d_in[0];
    const float* wq        = (const float*)d_in[1];
    const float* bq        = (const float*)d_in[2];
    const float* bn_w      = (const float*)d_in[3];
    const float* bn_b      = (const float*)d_in[4];
    const float* bn_mean   = (const float*)d_in[5];
    const float* bn_var    = (const float*)d_in[6];
    const float* sub_keys  = (const float*)d_in[7];
    const float* expert_w  = (const float*)d_in[8];
    const float* wo        = (const float*)d_in[9];
    const float* bo        = (const float*)d_in[10];
    const float* in_proj_w = (const float*)d_in[11];
    const float* in_proj_b = (const float*)d_in[12];
    const float* attn_ow   = (const float*)d_in[13];
    const float* attn_ob   = (const float*)d_in[14];
    const float* rms_w     = (const float*)d_in[15];

    float* y      = (float*)d_out;                       // (2,512,1024)
    float* attn_w = (float*)d_out + (size_t)NTOK * DMODEL; // (2,512,512)

    void *p_q, *p_qkv, *p_peer, *p_peer_proj, *p_ao, *p_ao_proj;
    cudaGetSymbolAddress(&p_q, g_q);
    cudaGetSymbolAddress(&p_qkv, g_qkv);
    cudaGetSymbolAddress(&p_peer, g_peer);
    cudaGetSymbolAddress(&p_peer_proj, g_peer_proj);
    cudaGetSymbolAddress(&p_ao, g_ao);
    cudaGetSymbolAddress(&p_ao_proj, g_ao_proj);

    // q = x @ wq^T + bq
    gemm_nt_bias<<<dim3(DMODEL / 64, NTOK / 128), 256>>>(
        x, wq, bq, (float*)p_q, NTOK, DMODEL, DMODEL);

    // PEER routing + expert mixture
    peer_route<<<NTOK * NHEADS, 128>>>(bn_w, bn_b, bn_mean, bn_var, sub_keys, expert_w);

    // qkv = x @ in_proj^T + b
    gemm_nt_bias<<<dim3(3 * DMODEL / 64, NTOK / 128), 256>>>(
        x, in_proj_w, in_proj_b, (float*)p_qkv, NTOK, 3 * DMODEL, DMODEL);

    // attention
    attn_scores<<<dim3(TSEQ / 16, BATCH * NHEADS), 256>>>();
    gemm_av<<<dim3(HD / 64, TSEQ / 128, BATCH * NHEADS), 256>>>();
    attn_mean<<<(BATCH * TSEQ * TSEQ) / 256, 256>>>(attn_w);

    // output projections
    gemm_nt_bias<<<dim3(DMODEL / 64, NTOK / 128), 256>>>(
        (const float*)p_peer, wo, bo, (float*)p_peer_proj, NTOK, DMODEL, DMODEL);
    gemm_nt_bias<<<dim3(DMODEL / 64, NTOK / 128), 256>>>(
        (const float*)p_ao, attn_ow, attn_ob, (float*)p_ao_proj, NTOK, DMODEL, DMODEL);

    // residual + rmsnorm
    final_rms<<<NTOK, 256>>>(x, rms_w, y);

    (void)in_sizes; (void)n_in; (void)out_size;
}

// round 3
// speedup vs baseline: 1.0442x; 1.0442x over previous
#include <cuda_runtime.h>
#include <cuda_bf16.h>
#include <math.h>
#include <stdint.h>

// ---------------- problem constants ----------------
#define BATCH   2
#define TSEQ    512
#define NTOK    1024      // BATCH*TSEQ
#define DMODEL  1024
#define NHEADS  8
#define DKEY    128
#define HK      1024      // NHEADS*DKEY
#define NSUB    128
#define TOPK    16
#define HD      128       // DMODEL/NHEADS

// ---------------- scratch (device globals; no allocation allowed) ----------------
__device__ __align__(128) float g_q[NTOK * HK];
__device__ __align__(128) float g_qkv[NTOK * 3 * DMODEL];
__device__ __align__(128) float g_peer[NTOK * HK];
__device__ __align__(128) float g_peer_proj[NTOK * DMODEL];
__device__ __align__(128) float g_att[BATCH * NHEADS * TSEQ * TSEQ];   // 16 MB
__device__ __align__(128) float g_ao[NTOK * DMODEL];
__device__ __align__(128) float g_ao_proj[NTOK * DMODEL];

// ---------------- helpers ----------------
__device__ __forceinline__ uint32_t smem_u32(const void* p) {
    uint32_t a;
    asm("{ .reg .u64 t; cvta.to.shared.u64 t, %1; cvt.u32.u64 %0, t; }"
        : "=r"(a) : "l"(p));
    return a;
}
__device__ __forceinline__ float to_tf32(float x) {
    float r;
    asm("cvt.rna.tf32.f32 %0, %1;" : "=f"(r) : "f"(x));
    return r;
}
#define LDSM4(r, addr) \
    asm volatile("ldmatrix.sync.aligned.m8n8.x4.shared.b16 {%0,%1,%2,%3}, [%4];" \
        : "=r"((r)[0]), "=r"((r)[1]), "=r"((r)[2]), "=r"((r)[3]) : "r"(addr))

#define MMA_TF32(d, a, b0, b1) \
    asm volatile("mma.sync.aligned.m16n8k8.row.col.f32.tf32.tf32.f32 " \
        "{%0,%1,%2,%3}, {%4,%5,%6,%7}, {%8,%9}, {%0,%1,%2,%3};" \
        : "+f"((d)[0]), "+f"((d)[1]), "+f"((d)[2]), "+f"((d)[3]) \
        : "r"((a)[0]), "r"((a)[1]), "r"((a)[2]), "r"((a)[3]), "r"(b0), "r"(b1))

// ============================================================================
// TF32 mma.sync "3M" GEMM: C[M,N] = A[M,K] @ B[N,K]^T + bias[N]  (fp32 I/O)
// CTA 128x128, BK=32, 8 warps (2 x 4), warp tile 64x32.
// D = Ah*Bh + Al*Bh + Ah*Bl  (error ~2^-22).
// SMEM: 4 tiles of 128 x 36 floats (pad 4 -> conflict-free ldmatrix) = 72KB.
// ============================================================================
#define GSTRIDE 36
#define GT_BYTES (128 * GSTRIDE * 4)
#define GEMM_MMA_SMEM (4 * GT_BYTES)

__global__ void __launch_bounds__(256) gemm_mma(
    const float* __restrict__ A, const float* __restrict__ B,
    const float* __restrict__ bias, float* __restrict__ C,
    int M, int N, int K)
{
    extern __shared__ float sm[];
    uint32_t ah_b = smem_u32(sm);
    uint32_t al_b = ah_b + GT_BYTES;
    uint32_t bh_b = al_b + GT_BYTES;
    uint32_t bl_b = bh_b + GT_BYTES;

    int t = threadIdx.x;
    int warp = t >> 5, lane = t & 31;
    int m0 = blockIdx.y * 128, n0 = blockIdx.x * 128;
    int wm = warp >> 2, wn = warp & 3;        // 2 x 4 warp grid

    float acc[4][4][4];
#pragma unroll
    for (int i = 0; i < 4; i++)
#pragma unroll
        for (int j = 0; j < 4; j++)
#pragma unroll
            for (int r = 0; r < 4; r++) acc[i][j][r] = 0.f;

    // per-thread ldmatrix addresses (constant across K loop except k offset)
    int a_row = wm * 64 + (lane & 15);
    int a_kof = ((lane >> 4) << 2);
    int b_row = wn * 32 + (lane & 7) + ((lane >> 4) << 3);
    int b_kof = (((lane >> 3) & 1) << 2);

    for (int k0 = 0; k0 < K; k0 += 32) {
        // ---- stage A/B 128x32 hi/lo into padded smem ----
#pragma unroll
        for (int ss = 0; ss < 2; ss++) {
            int v = t + ss * 256;
            int row = v >> 1, c4 = (v & 1) * 4;   // 2 float4 per row? no: 8 per row
            (void)row; (void)c4;
        }
#pragma unroll
        for (int ss = 0; ss < 4; ss++) {
            int v = t + ss * 256;
            int row = v >> 3, c4 = v & 7;         // 128 rows x 8 float4
            uint32_t so = (uint32_t)(row * GSTRIDE + c4 * 4) * 4u;
            {
                float4 a = *(const float4*)(A + (size_t)(m0 + row) * K + k0 + c4 * 4);
                float4 h, l;
                h.x = to_tf32(a.x); l.x = to_tf32(a.x - h.x);
                h.y = to_tf32(a.y); l.y = to_tf32(a.y - h.y);
                h.z = to_tf32(a.z); l.z = to_tf32(a.z - h.z);
                h.w = to_tf32(a.w); l.w = to_tf32(a.w - h.w);
                asm volatile("st.shared.v4.b32 [%0], {%1,%2,%3,%4};"
                             :: "r"(ah_b + so), "f"(h.x), "f"(h.y), "f"(h.z), "f"(h.w) : "memory");
                asm volatile("st.shared.v4.b32 [%0], {%1,%2,%3,%4};"
                             :: "r"(al_b + so), "f"(l.x), "f"(l.y), "f"(l.z), "f"(l.w) : "memory");
            }
            {
                float4 a = *(const float4*)(B + (size_t)(n0 + row) * K + k0 + c4 * 4);
                float4 h, l;
                h.x = to_tf32(a.x); l.x = to_tf32(a.x - h.x);
                h.y = to_tf32(a.y); l.y = to_tf32(a.y - h.y);
                h.z = to_tf32(a.z); l.z = to_tf32(a.z - h.z);
                h.w = to_tf32(a.w); l.w = to_tf32(a.w - h.w);
                asm volatile("st.shared.v4.b32 [%0], {%1,%2,%3,%4};"
                             :: "r"(bh_b + so), "f"(h.x), "f"(h.y), "f"(h.z), "f"(h.w) : "memory");
                asm volatile("st.shared.v4.b32 [%0], {%1,%2,%3,%4};"
                             :: "r"(bl_b + so), "f"(l.x), "f"(l.y), "f"(l.z), "f"(l.w) : "memory");
            }
        }
        __syncthreads();

        // ---- compute: 4 k-steps of 8 ----
#pragma unroll
        for (int ks = 0; ks < 4; ks++) {
            uint32_t ahf[4][4], alf[4][4];
            uint32_t bhf[2][4], blf[2][4];
            int ak = ks * 8 + a_kof;
            int bk = ks * 8 + b_kof;
#pragma unroll
            for (int mt = 0; mt < 4; mt++) {
                uint32_t off = (uint32_t)((a_row + mt * 16) * GSTRIDE + ak) * 4u;
                LDSM4(ahf[mt], ah_b + off);
                LDSM4(alf[mt], al_b + off);
            }
#pragma unroll
            for (int bp = 0; bp < 2; bp++) {
                uint32_t off = (uint32_t)((b_row + bp * 16) * GSTRIDE + bk) * 4u;
                LDSM4(bhf[bp], bh_b + off);
                LDSM4(blf[bp], bl_b + off);
            }
#pragma unroll
            for (int mt = 0; mt < 4; mt++) {
#pragma unroll
                for (int nt = 0; nt < 4; nt++) {
                    uint32_t b0h = bhf[nt >> 1][(nt & 1) * 2];
                    uint32_t b1h = bhf[nt >> 1][(nt & 1) * 2 + 1];
                    uint32_t b0l = blf[nt >> 1][(nt & 1) * 2];
                    uint32_t b1l = blf[nt >> 1][(nt & 1) * 2 + 1];
                    MMA_TF32(acc[mt][nt], ahf[mt], b0h, b1h);
                    MMA_TF32(acc[mt][nt], alf[mt], b0h, b1h);
                    MMA_TF32(acc[mt][nt], ahf[mt], b0l, b1l);
                }
            }
        }
        __syncthreads();
    }

    // ---- epilogue: bias add + store ----
    int g = lane >> 2, c = lane & 3;
#pragma unroll
    for (int mt = 0; mt < 4; mt++) {
#pragma unroll
        for (int nt = 0; nt < 4; nt++) {
            int row = m0 + wm * 64 + mt * 16 + g;
            int col = n0 + wn * 32 + nt * 8 + 2 * c;
            float b0 = bias[col], b1 = bias[col + 1];
            float2 v0 = make_float2(acc[mt][nt][0] + b0, acc[mt][nt][1] + b1);
            float2 v1 = make_float2(acc[mt][nt][2] + b0, acc[mt][nt][3] + b1);
            *(float2*)(C + (size_t)row * N + col)       = v0;
            *(float2*)(C + (size_t)(row + 8) * N + col) = v1;
        }
    }
}

// ============================================================================
// PEER routing (unchanged)
// ============================================================================
__global__ void __launch_bounds__(128) peer_route(
    const float* __restrict__ bn_w, const float* __restrict__ bn_b,
    const float* __restrict__ bn_mean, const float* __restrict__ bn_var,
    const float* __restrict__ sub_keys, const float* __restrict__ expert_w)
{
    int token = blockIdx.x >> 3;
    int head  = blockIdx.x & 7;
    int tid   = threadIdx.x;

    __shared__ float q[128];
    __shared__ float s1[128], s2[128];
    __shared__ float v1[16], v2[16];
    __shared__ int   i1[16], i2[16];
    __shared__ float cval[256];
    __shared__ int   cidx[256];
    __shared__ int   sel[16];
    __shared__ float simv[16];
    __shared__ float rw[16];
    __shared__ float ews[16][128];

    int c = head * 128 + tid;
    float qraw = g_q[(size_t)token * HK + c];
    float qb = (qraw - bn_mean[c]) * rsqrtf(bn_var[c] + 1e-5f) * bn_w[c] + bn_b[c];
    q[tid] = qb;
    __syncthreads();

    float a1 = 0.f, a2 = 0.f;
    const float* k1p = sub_keys + (size_t)tid * 64;
    const float* k2p = sub_keys + (size_t)NSUB * 64 + (size_t)tid * 64;
#pragma unroll 8
    for (int i = 0; i < 64; i++) {
        a1 += q[i]      * k1p[i];
        a2 += q[64 + i] * k2p[i];
    }
    s1[tid] = a1; s2[tid] = a2;
    __syncthreads();

    int r1 = 0, r2 = 0;
    for (int j = 0; j < 128; j++) {
        float x1 = s1[j]; r1 += (x1 > a1) || (x1 == a1 && j < tid);
        float x2 = s2[j]; r2 += (x2 > a2) || (x2 == a2 && j < tid);
    }
    if (r1 < 16) { v1[r1] = a1; i1[r1] = tid; }
    if (r2 < 16) { v2[r2] = a2; i2[r2] = tid; }
    __syncthreads();

    for (int p = tid; p < 256; p += 128) {
        int a = p >> 4, bb = p & 15;
        cval[p] = v1[a] + v2[bb];
        cidx[p] = i1[a] * NSUB + i2[bb];
    }
    __syncthreads();
    for (int p = tid; p < 256; p += 128) {
        float v = cval[p];
        int r = 0;
        for (int j = 0; j < 256; j++) {
            float w = cval[j];
            r += (w > v) || (w == v && j < p);
        }
        if (r < 16) sel[r] = cidx[p];
    }
    __syncthreads();

#pragma unroll
    for (int k = 0; k < 16; k++)
        ews[k][tid] = expert_w[(size_t)sel[k] * DKEY + tid];
    __syncthreads();

    int k8 = tid >> 3, l8 = tid & 7;
    float part = 0.f;
#pragma unroll
    for (int i = 0; i < 16; i++) {
        int d = l8 * 16 + i;
        part += q[d] * ews[k8][d];
    }
    part += __shfl_down_sync(0xffffffffu, part, 4);
    part += __shfl_down_sync(0xffffffffu, part, 2);
    part += __shfl_down_sync(0xffffffffu, part, 1);
    if (l8 == 0) simv[k8] = part;
    __syncthreads();

    if (tid == 0) {
        float m = -INFINITY;
#pragma unroll
        for (int k = 0; k < 16; k++) m = fmaxf(m, simv[k]);
        float e[16]; float s = 0.f;
#pragma unroll
        for (int k = 0; k < 16; k++) { e[k] = expf(simv[k] - m); s += e[k]; }
        float inv = 1.f / s;
#pragma unroll
        for (int k = 0; k < 16; k++) rw[k] = e[k] * inv;
    }
    __syncthreads();

    float o = 0.f;
#pragma unroll
    for (int k = 0; k < 16; k++) o += rw[k] * ews[k][tid];
    g_peer[(size_t)token * HK + c] = o;
}

// ============================================================================
// Attention scores + softmax (vectorized LDS.128 inner loop)
// ============================================================================
__global__ void __launch_bounds__(256) attn_scores()
{
    int z = blockIdx.y;          // b*8 + h
    int b = z >> 3, h = z & 7;
    int q0 = blockIdx.x * 16;
    int t = threadIdx.x;

    __shared__ float qs[16][128];
    __shared__ float Ks[32][132];

#pragma unroll
    for (int s = 0; s < 2; s++) {
        int v = t + s * 256;
        int r = v >> 5, c4 = (v & 31) * 4;
        float4 val = *(const float4*)&g_qkv[(size_t)(b * TSEQ + q0 + r) * (3 * DMODEL) + h * HD + c4];
        *(float4*)&qs[r][c4] = val;
    }
    __syncthreads();

    int j  = t & 15;
    int rr = t >> 4;
    float sreg[32];

    for (int kt = 0; kt < 16; kt++) {
#pragma unroll
        for (int s = 0; s < 4; s++) {
            int v = t + s * 256;
            int kr = v >> 5, c4 = (v & 31) * 4;
            float4 val = *(const float4*)&g_qkv[(size_t)(b * TSEQ + kt * 32 + kr) * (3 * DMODEL) + DMODEL + h * HD + c4];
            Ks[kr][c4 + 0] = val.x; Ks[kr][c4 + 1] = val.y;
            Ks[kr][c4 + 2] = val.z; Ks[kr][c4 + 3] = val.w;
        }
        __syncthreads();
        float acc1 = 0.f, acc2 = 0.f;
        const float4* qr  = (const float4*)&qs[rr][0];
        const float4* ka4 = (const float4*)&Ks[j][0];
        const float4* kb4 = (const float4*)&Ks[j + 16][0];
#pragma unroll
        for (int i = 0; i < 32; i++) {
            float4 qv = qr[i];
            float4 a  = ka4[i];
            float4 bb = kb4[i];
            acc1 += qv.x * a.x + qv.y * a.y + qv.z * a.z + qv.w * a.w;
            acc2 += qv.x * bb.x + qv.y * bb.y + qv.z * bb.z + qv.w * bb.w;
        }
        sreg[2 * kt]     = acc1;
        sreg[2 * kt + 1] = acc2;
        __syncthreads();
    }

    const float scale = 0.08838834764831845f;  // 1/sqrt(128)
#pragma unroll
    for (int i = 0; i < 32; i++) sreg[i] *= scale;

    float m = -INFINITY;
#pragma unroll
    for (int i = 0; i < 32; i++) m = fmaxf(m, sreg[i]);
#pragma unroll
    for (int off = 8; off; off >>= 1)
        m = fmaxf(m, __shfl_xor_sync(0xffffffffu, m, off));
    float sum = 0.f;
#pragma unroll
    for (int i = 0; i < 32; i++) { sreg[i] = expf(sreg[i] - m); sum += sreg[i]; }
#pragma unroll
    for (int off = 8; off; off >>= 1)
        sum += __shfl_xor_sync(0xffffffffu, sum, off);
    float inv = 1.f / sum;

    float* arow = g_att + ((size_t)z * TSEQ + q0 + rr) * TSEQ;
#pragma unroll
    for (int kt = 0; kt < 16; kt++) {
        arow[kt * 32 + j]      = sreg[2 * kt] * inv;
        arow[kt * 32 + 16 + j] = sreg[2 * kt + 1] * inv;
    }
}

// ============================================================================
// AV GEMM (NN, strided) — SIMT
// ============================================================================
__global__ void __launch_bounds__(256) gemm_av()
{
    int z = blockIdx.z;
    int b = z >> 3, h = z & 7;
    const float* A  = g_att + (size_t)z * TSEQ * TSEQ;
    const float* Bb = g_qkv + (size_t)b * TSEQ * (3 * DMODEL) + 2 * DMODEL + h * HD;
    float* Cb = g_ao + (size_t)b * TSEQ * DMODEL + h * HD;

    __shared__ float As[16][128];
    __shared__ float Bs[16][64];
    int t  = threadIdx.x;
    int m0 = blockIdx.y * 128;
    int n0 = blockIdx.x * 64;
    int tx = t & 15, ty = t >> 4;

    float acc[8][4];
#pragma unroll
    for (int i = 0; i < 8; i++)
#pragma unroll
        for (int j = 0; j < 4; j++) acc[i][j] = 0.f;

    for (int k0 = 0; k0 < TSEQ; k0 += 16) {
#pragma unroll
        for (int s = 0; s < 2; s++) {
            int v = t + s * 256;
            int row = v >> 2, c4 = (v & 3) * 4;
            float4 a = *(const float4*)(A + (size_t)(m0 + row) * TSEQ + k0 + c4);
            As[c4 + 0][row] = a.x; As[c4 + 1][row] = a.y;
            As[c4 + 2][row] = a.z; As[c4 + 3][row] = a.w;
        }
        {
            int kr = t >> 4, c4 = (t & 15) * 4;
            float4 bv = *(const float4*)(Bb + (size_t)(k0 + kr) * (3 * DMODEL) + n0 + c4);
            *(float4*)&Bs[kr][c4] = bv;
        }
        __syncthreads();
#pragma unroll
        for (int kk = 0; kk < 16; kk++) {
            float ar[8], br[4];
#pragma unroll
            for (int i = 0; i < 8; i++) ar[i] = As[kk][ty * 8 + i];
#pragma unroll
            for (int jj = 0; jj < 4; jj++) br[jj] = Bs[kk][tx * 4 + jj];
#pragma unroll
            for (int i = 0; i < 8; i++)
#pragma unroll
                for (int jj = 0; jj < 4; jj++) acc[i][jj] += ar[i] * br[jj];
        }
        __syncthreads();
    }
#pragma unroll
    for (int i = 0; i < 8; i++) {
        int m = m0 + ty * 8 + i;
#pragma unroll
        for (int jj = 0; jj < 4; jj++) {
            Cb[(size_t)m * DMODEL + n0 + tx * 4 + jj] = acc[i][jj];
        }
    }
}

// mean over heads for attn_weights output
__global__ void __launch_bounds__(256) attn_mean(float* __restrict__ out)
{
    int idx = blockIdx.x * 256 + threadIdx.x;
    int b   = idx / (TSEQ * TSEQ);
    int rem = idx - b * (TSEQ * TSEQ);
    float s = 0.f;
#pragma unroll
    for (int h = 0; h < 8; h++)
        s += g_att[((size_t)(b * 8 + h)) * (TSEQ * TSEQ) + rem];
    out[idx] = s * 0.125f;
}

// final: y = rmsnorm(x + peer_proj + ao_proj) * rms_w
__global__ void __launch_bounds__(256) final_rms(
    const float* __restrict__ x, const float* __restrict__ rms_w,
    float* __restrict__ y)
{
    int token = blockIdx.x;
    int t = threadIdx.x;
    size_t base = (size_t)token * DMODEL;
    float v[4];
    float ss = 0.f;
#pragma unroll
    for (int u = 0; u < 4; u++) {
        int c = t + u * 256;
        float s = x[base + c] + g_peer_proj[base + c] + g_ao_proj[base + c];
        v[u] = s;
        ss += s * s;
    }
#pragma unroll
    for (int off = 16; off; off >>= 1)
        ss += __shfl_xor_sync(0xffffffffu, ss, off);
    __shared__ float red[8];
    __shared__ float stot;
    if ((t & 31) == 0) red[t >> 5] = ss;
    __syncthreads();
    if (t == 0) {
        float s = 0.f;
#pragma unroll
        for (int i = 0; i < 8; i++) s += red[i];
        stot = rsqrtf(s * (1.f / DMODEL) + 1e-6f);
    }
    __syncthreads();
    float inv = stot;
#pragma unroll
    for (int u = 0; u < 4; u++) {
        int c = t + u * 256;
        y[base + c] = v[u] * inv * rms_w[c];
    }
}

// ============================================================================
extern "C" void kernel_launch(void* const* d_in, const int* in_sizes, int n_in,
                              void* d_out, int out_size)
{
    const float* x         = (const float*)d_in[0];
    const float* wq        = (const float*)d_in[1];
    const float* bq        = (const float*)d_in[2];
    const float* bn_w      = (const float*)d_in[3];
    const float* bn_b      = (const float*)d_in[4];
    const float* bn_mean   = (const float*)d_in[5];
    const float* bn_var    = (const float*)d_in[6];
    const float* sub_keys  = (const float*)d_in[7];
    const float* expert_w  = (const float*)d_in[8];
    const float* wo        = (const float*)d_in[9];
    const float* bo        = (const float*)d_in[10];
    const float* in_proj_w = (const float*)d_in[11];
    const float* in_proj_b = (const float*)d_in[12];
    const float* attn_ow   = (const float*)d_in[13];
    const float* attn_ob   = (const float*)d_in[14];
    const float* rms_w     = (const float*)d_in[15];

    float* y      = (float*)d_out;                         // (2,512,1024)
    float* attn_w = (float*)d_out + (size_t)NTOK * DMODEL; // (2,512,512)

    void *p_q, *p_qkv, *p_peer, *p_peer_proj, *p_ao, *p_ao_proj;
    cudaGetSymbolAddress(&p_q, g_q);
    cudaGetSymbolAddress(&p_qkv, g_qkv);
    cudaGetSymbolAddress(&p_peer, g_peer);
    cudaGetSymbolAddress(&p_peer_proj, g_peer_proj);
    cudaGetSymbolAddress(&p_ao, g_ao);
    cudaGetSymbolAddress(&p_ao_proj, g_ao_proj);

    cudaFuncSetAttribute(gemm_mma, cudaFuncAttributeMaxDynamicSharedMemorySize,
                         GEMM_MMA_SMEM);

    // q = x @ wq^T + bq           (mma.sync tf32 x3)
    gemm_mma<<<dim3(DMODEL / 128, NTOK / 128), 256, GEMM_MMA_SMEM>>>(
        x, wq, bq, (float*)p_q, NTOK, DMODEL, DMODEL);

    // qkv = x @ in_proj^T + b
    gemm_mma<<<dim3(3 * DMODEL / 128, NTOK / 128), 256, GEMM_MMA_SMEM>>>(
        x, in_proj_w, in_proj_b, (float*)p_qkv, NTOK, 3 * DMODEL, DMODEL);

    // PEER routing + expert mixture
    peer_route<<<NTOK * NHEADS, 128>>>(bn_w, bn_b, bn_mean, bn_var, sub_keys, expert_w);

    // attention
    attn_scores<<<dim3(TSEQ / 16, BATCH * NHEADS), 256>>>();
    gemm_av<<<dim3(HD / 64, TSEQ / 128, BATCH * NHEADS), 256>>>();
    attn_mean<<<(BATCH * TSEQ * TSEQ) / 256, 256>>>(attn_w);

    // output projections
    gemm_mma<<<dim3(DMODEL / 128, NTOK / 128), 256, GEMM_MMA_SMEM>>>(
        (const float*)p_peer, wo, bo, (float*)p_peer_proj, NTOK, DMODEL, DMODEL);
    gemm_mma<<<dim3(DMODEL / 128, NTOK / 128), 256, GEMM_MMA_SMEM>>>(
        (const float*)p_ao, attn_ow, attn_ob, (float*)p_ao_proj, NTOK, DMODEL, DMODEL);

    // residual + rmsnorm
    final_rms<<<NTOK, 256>>>(x, rms_w, y);

    (void)in_sizes; (void)n_in; (void)out_size;
}

// round 4
// speedup vs baseline: 1.2451x; 1.1925x over previous
#include <cuda_runtime.h>
#include <cuda_bf16.h>
#include <math.h>
#include <stdint.h>

// ---------------- problem constants ----------------
#define BATCH   2
#define TSEQ    512
#define NTOK    1024      // BATCH*TSEQ
#define DMODEL  1024
#define NHEADS  8
#define DKEY    128
#define HK      1024      // NHEADS*DKEY
#define NSUB    128
#define TOPK    16
#define HD      128       // DMODEL/NHEADS

// ---------------- scratch (device globals; no allocation allowed) ----------------
__device__ __align__(128) float g_q[NTOK * HK];
__device__ __align__(128) float g_qkv[NTOK * 3 * DMODEL];
__device__ __align__(128) float g_peer_proj[NTOK * DMODEL];
__device__ __align__(128) float g_att[BATCH * NHEADS * TSEQ * TSEQ];   // 16 MB
__device__ __align__(128) float g_ao_proj[NTOK * DMODEL];

// bf16 split (hi/lo) buffers
__device__ __align__(128) __nv_bfloat16 g_x_hi[NTOK * DMODEL],   g_x_lo[NTOK * DMODEL];
__device__ __align__(128) __nv_bfloat16 g_wq_hi[DMODEL * DMODEL], g_wq_lo[DMODEL * DMODEL];
__device__ __align__(128) __nv_bfloat16 g_ip_hi[3 * DMODEL * DMODEL], g_ip_lo[3 * DMODEL * DMODEL];
__device__ __align__(128) __nv_bfloat16 g_wo_hi[DMODEL * DMODEL], g_wo_lo[DMODEL * DMODEL];
__device__ __align__(128) __nv_bfloat16 g_aow_hi[DMODEL * DMODEL], g_aow_lo[DMODEL * DMODEL];
__device__ __align__(128) __nv_bfloat16 g_peer_hi[NTOK * HK],     g_peer_lo[NTOK * HK];
__device__ __align__(128) __nv_bfloat16 g_ao_hi[NTOK * DMODEL],   g_ao_lo[NTOK * DMODEL];

// ---------------- helpers ----------------
__device__ __forceinline__ uint32_t smem_u32(const void* p) {
    uint32_t a;
    asm("{ .reg .u64 t; cvta.to.shared.u64 t, %1; cvt.u32.u64 %0, t; }"
        : "=r"(a) : "l"(p));
    return a;
}
#define LDSM4(r, addr) \
    asm volatile("ldmatrix.sync.aligned.m8n8.x4.shared.b16 {%0,%1,%2,%3}, [%4];" \
        : "=r"((r)[0]), "=r"((r)[1]), "=r"((r)[2]), "=r"((r)[3]) : "r"(addr))

#define MMA_BF16(d, a, b0, b1) \
    asm volatile("mma.sync.aligned.m16n8k16.row.col.f32.bf16.bf16.f32 " \
        "{%0,%1,%2,%3}, {%4,%5,%6,%7}, {%8,%9}, {%0,%1,%2,%3};" \
        : "+f"((d)[0]), "+f"((d)[1]), "+f"((d)[2]), "+f"((d)[3]) \
        : "r"((a)[0]), "r"((a)[1]), "r"((a)[2]), "r"((a)[3]), "r"(b0), "r"(b1))

#define CP16(dst, src) \
    asm volatile("cp.async.cg.shared.global [%0], [%1], 16;" :: "r"(dst), "l"(src))
#define CP_COMMIT() asm volatile("cp.async.commit_group;" ::: "memory")
#define CP_WAIT1()  asm volatile("cp.async.wait_group 1;" ::: "memory")

// ============================================================================
// split fp32 -> bf16 hi/lo  (vectorized; n must be multiple of 1024)
// ============================================================================
__global__ void __launch_bounds__(256) split_bf16(
    const float* __restrict__ src, __nv_bfloat16* __restrict__ hi,
    __nv_bfloat16* __restrict__ lo)
{
    int i = blockIdx.x * 256 + threadIdx.x;
    float4 v = ((const float4*)src)[i];
    float vv[4] = {v.x, v.y, v.z, v.w};
    __nv_bfloat16 h[4], l[4];
#pragma unroll
    for (int k = 0; k < 4; k++) {
        h[k] = __float2bfloat16(vv[k]);
        l[k] = __float2bfloat16(vv[k] - __bfloat162float(h[k]));
    }
    __nv_bfloat162* hp = (__nv_bfloat162*)hi;
    __nv_bfloat162* lp = (__nv_bfloat162*)lo;
    hp[2 * i]     = __nv_bfloat162(h[0], h[1]);
    hp[2 * i + 1] = __nv_bfloat162(h[2], h[3]);
    lp[2 * i]     = __nv_bfloat162(l[0], l[1]);
    lp[2 * i + 1] = __nv_bfloat162(l[2], l[3]);
}

// ============================================================================
// bf16-split "3M" GEMM: C[M,N] = A[M,K] @ B[N,K]^T + bias[N]  (fp32 out)
// CTA tile 64x128, BK=32, 8 warps (2x4), warp tile 32x32.
// 3-stage cp.async pipeline. smem rows padded to 40 bf16 (conflict-free LDSM).
// ============================================================================
#define AST      40
#define A_TILE_B (64 * AST * 2)     // 5120 B
#define B_TILE_B (128 * AST * 2)    // 10240 B
#define STAGE_B  (2 * A_TILE_B + 2 * B_TILE_B)   // 30720 B
#define GEMM_SMEM (3 * STAGE_B)     // 92160 B

__global__ void __launch_bounds__(256) gemm_bf16(
    const __nv_bfloat16* __restrict__ Ahi, const __nv_bfloat16* __restrict__ Alo,
    const __nv_bfloat16* __restrict__ Bhi, const __nv_bfloat16* __restrict__ Blo,
    const float* __restrict__ bias, float* __restrict__ C,
    int M, int N, int K)
{
    extern __shared__ char smc[];
    uint32_t base = smem_u32(smc);
    int t = threadIdx.x, warp = t >> 5, lane = t & 31;
    int m0 = blockIdx.y * 64, n0 = blockIdx.x * 128;
    int wm = warp >> 2, wn = warp & 3;

    float acc[2][4][4];
#pragma unroll
    for (int i = 0; i < 2; i++)
#pragma unroll
        for (int j = 0; j < 4; j++)
#pragma unroll
            for (int r = 0; r < 4; r++) acc[i][j][r] = 0.f;

    const int niter = K >> 5;

    // ---- async stage loader ----
    auto issue = [&](int it) {
        uint32_t sb = base + (it % 3) * STAGE_B;
        int k0 = it << 5;
        {   // A: 64 rows x 4 chunks = 256
            int row = t >> 2, j = t & 3;
            const char* sh = (const char*)(Ahi + (size_t)(m0 + row) * K + k0) + j * 16;
            const char* sl = (const char*)(Alo + (size_t)(m0 + row) * K + k0) + j * 16;
            uint32_t d = sb + (uint32_t)(row * 80 + j * 16);
            CP16(d, sh);
            CP16(d + A_TILE_B, sl);
        }
#pragma unroll
        for (int s = 0; s < 2; s++) {   // B: 128 rows x 4 chunks = 512
            int c = t + s * 256;
            int row = c >> 2, j = c & 3;
            const char* sh = (const char*)(Bhi + (size_t)(n0 + row) * K + k0) + j * 16;
            const char* sl = (const char*)(Blo + (size_t)(n0 + row) * K + k0) + j * 16;
            uint32_t d = sb + 2 * A_TILE_B + (uint32_t)(row * 80 + j * 16);
            CP16(d, sh);
            CP16(d + B_TILE_B, sl);
        }
    };

    issue(0); CP_COMMIT();
    issue(1); CP_COMMIT();

    uint32_t a_off = (uint32_t)((wm * 32 + (lane & 15)) * 80 + (lane >> 4) * 16);
    uint32_t b_off = (uint32_t)((wn * 32 + (lane & 15)) * 80 + (lane >> 4) * 16);

    for (int it = 0; it < niter; ++it) {
        CP_WAIT1();
        __syncthreads();
        if (it + 2 < niter) issue(it + 2);
        CP_COMMIT();

        uint32_t sb = base + (it % 3) * STAGE_B;
        uint32_t sa_h = sb, sa_l = sb + A_TILE_B;
        uint32_t sb_h = sb + 2 * A_TILE_B, sb_l = sb_h + B_TILE_B;

#pragma unroll
        for (int ks = 0; ks < 2; ks++) {
            uint32_t kb = ks * 32;
            uint32_t ah[2][4], al[2][4], bh[2][4], bl[2][4];
#pragma unroll
            for (int mt = 0; mt < 2; mt++) {
                uint32_t o = a_off + mt * 16 * 80 + kb;
                LDSM4(ah[mt], sa_h + o);
                LDSM4(al[mt], sa_l + o);
            }
#pragma unroll
            for (int bt = 0; bt < 2; bt++) {
                uint32_t o = b_off + bt * 16 * 80 + kb;
                LDSM4(bh[bt], sb_h + o);
                LDSM4(bl[bt], sb_l + o);
            }
#pragma unroll
            for (int mt = 0; mt < 2; mt++) {
#pragma unroll
                for (int nt = 0; nt < 4; nt++) {
                    int bt = nt >> 1, s2 = nt & 1;
                    MMA_BF16(acc[mt][nt], ah[mt], bh[bt][s2], bh[bt][s2 + 2]);
                    MMA_BF16(acc[mt][nt], al[mt], bh[bt][s2], bh[bt][s2 + 2]);
                    MMA_BF16(acc[mt][nt], ah[mt], bl[bt][s2], bl[bt][s2 + 2]);
                }
            }
        }
        __syncthreads();
    }

    // ---- epilogue ----
    int g = lane >> 2, c2 = lane & 3;
#pragma unroll
    for (int mt = 0; mt < 2; mt++) {
#pragma unroll
        for (int nt = 0; nt < 4; nt++) {
            int row = m0 + wm * 32 + mt * 16 + g;
            int col = n0 + wn * 32 + nt * 8 + 2 * c2;
            float b0 = bias[col], b1 = bias[col + 1];
            *(float2*)(C + (size_t)row * N + col) =
                make_float2(acc[mt][nt][0] + b0, acc[mt][nt][1] + b1);
            *(float2*)(C + (size_t)(row + 8) * N + col) =
                make_float2(acc[mt][nt][2] + b0, acc[mt][nt][3] + b1);
        }
    }
}

// ============================================================================
// PEER routing (writes bf16 hi/lo output)
// ============================================================================
__global__ void __launch_bounds__(128) peer_route(
    const float* __restrict__ bn_w, const float* __restrict__ bn_b,
    const float* __restrict__ bn_mean, const float* __restrict__ bn_var,
    const float* __restrict__ sub_keys, const float* __restrict__ expert_w)
{
    int token = blockIdx.x >> 3;
    int head  = blockIdx.x & 7;
    int tid   = threadIdx.x;

    __shared__ float q[128];
    __shared__ float s1[128], s2[128];
    __shared__ float v1[16], v2[16];
    __shared__ int   i1[16], i2[16];
    __shared__ float cval[256];
    __shared__ int   cidx[256];
    __shared__ int   sel[16];
    __shared__ float simv[16];
    __shared__ float rw[16];
    __shared__ float ews[16][128];

    int c = head * 128 + tid;
    float qraw = g_q[(size_t)token * HK + c];
    float qb = (qraw - bn_mean[c]) * rsqrtf(bn_var[c] + 1e-5f) * bn_w[c] + bn_b[c];
    q[tid] = qb;
    __syncthreads();

    float a1 = 0.f, a2 = 0.f;
    const float* k1p = sub_keys + (size_t)tid * 64;
    const float* k2p = sub_keys + (size_t)NSUB * 64 + (size_t)tid * 64;
#pragma unroll 8
    for (int i = 0; i < 64; i++) {
        a1 += q[i]      * k1p[i];
        a2 += q[64 + i] * k2p[i];
    }
    s1[tid] = a1; s2[tid] = a2;
    __syncthreads();

    int r1 = 0, r2 = 0;
    for (int j = 0; j < 128; j++) {
        float x1 = s1[j]; r1 += (x1 > a1) || (x1 == a1 && j < tid);
        float x2 = s2[j]; r2 += (x2 > a2) || (x2 == a2 && j < tid);
    }
    if (r1 < 16) { v1[r1] = a1; i1[r1] = tid; }
    if (r2 < 16) { v2[r2] = a2; i2[r2] = tid; }
    __syncthreads();

    for (int p = tid; p < 256; p += 128) {
        int a = p >> 4, bb = p & 15;
        cval[p] = v1[a] + v2[bb];
        cidx[p] = i1[a] * NSUB + i2[bb];
    }
    __syncthreads();
    for (int p = tid; p < 256; p += 128) {
        float v = cval[p];
        int r = 0;
        for (int j = 0; j < 256; j++) {
            float w = cval[j];
            r += (w > v) || (w == v && j < p);
        }
        if (r < 16) sel[r] = cidx[p];
    }
    __syncthreads();

#pragma unroll
    for (int k = 0; k < 16; k++)
        ews[k][tid] = expert_w[(size_t)sel[k] * DKEY + tid];
    __syncthreads();

    int k8 = tid >> 3, l8 = tid & 7;
    float part = 0.f;
#pragma unroll
    for (int i = 0; i < 16; i++) {
        int d = l8 * 16 + i;
        part += q[d] * ews[k8][d];
    }
    part += __shfl_down_sync(0xffffffffu, part, 4);
    part += __shfl_down_sync(0xffffffffu, part, 2);
    part += __shfl_down_sync(0xffffffffu, part, 1);
    if (l8 == 0) simv[k8] = part;
    __syncthreads();

    if (tid == 0) {
        float m = -INFINITY;
#pragma unroll
        for (int k = 0; k < 16; k++) m = fmaxf(m, simv[k]);
        float e[16]; float s = 0.f;
#pragma unroll
        for (int k = 0; k < 16; k++) { e[k] = expf(simv[k] - m); s += e[k]; }
        float inv = 1.f / s;
#pragma unroll
        for (int k = 0; k < 16; k++) rw[k] = e[k] * inv;
    }
    __syncthreads();

    float o = 0.f;
#pragma unroll
    for (int k = 0; k < 16; k++) o += rw[k] * ews[k][tid];
    size_t idx = (size_t)token * HK + c;
    __nv_bfloat16 h = __float2bfloat16(o);
    g_peer_hi[idx] = h;
    g_peer_lo[idx] = __float2bfloat16(o - __bfloat162float(h));
}

// ============================================================================
// Attention scores + softmax
// ============================================================================
__global__ void __launch_bounds__(256) attn_scores()
{
    int z = blockIdx.y;          // b*8 + h
    int b = z >> 3, h = z & 7;
    int q0 = blockIdx.x * 16;
    int t = threadIdx.x;

    __shared__ float qs[16][128];
    __shared__ float Ks[32][132];

#pragma unroll
    for (int s = 0; s < 2; s++) {
        int v = t + s * 256;
        int r = v >> 5, c4 = (v & 31) * 4;
        float4 val = *(const float4*)&g_qkv[(size_t)(b * TSEQ + q0 + r) * (3 * DMODEL) + h * HD + c4];
        *(float4*)&qs[r][c4] = val;
    }
    __syncthreads();

    int j  = t & 15;
    int rr = t >> 4;
    float sreg[32];

    for (int kt = 0; kt < 16; kt++) {
#pragma unroll
        for (int s = 0; s < 4; s++) {
            int v = t + s * 256;
            int kr = v >> 5, c4 = (v & 31) * 4;
            float4 val = *(const float4*)&g_qkv[(size_t)(b * TSEQ + kt * 32 + kr) * (3 * DMODEL) + DMODEL + h * HD + c4];
            Ks[kr][c4 + 0] = val.x; Ks[kr][c4 + 1] = val.y;
            Ks[kr][c4 + 2] = val.z; Ks[kr][c4 + 3] = val.w;
        }
        __syncthreads();
        float acc1 = 0.f, acc2 = 0.f;
        const float4* qr  = (const float4*)&qs[rr][0];
        const float4* ka4 = (const float4*)&Ks[j][0];
        const float4* kb4 = (const float4*)&Ks[j + 16][0];
#pragma unroll
        for (int i = 0; i < 32; i++) {
            float4 qv = qr[i];
            float4 a  = ka4[i];
            float4 bb = kb4[i];
            acc1 += qv.x * a.x + qv.y * a.y + qv.z * a.z + qv.w * a.w;
            acc2 += qv.x * bb.x + qv.y * bb.y + qv.z * bb.z + qv.w * bb.w;
        }
        sreg[2 * kt]     = acc1;
        sreg[2 * kt + 1] = acc2;
        __syncthreads();
    }

    const float scale = 0.08838834764831845f;  // 1/sqrt(128)
#pragma unroll
    for (int i = 0; i < 32; i++) sreg[i] *= scale;

    float m = -INFINITY;
#pragma unroll
    for (int i = 0; i < 32; i++) m = fmaxf(m, sreg[i]);
#pragma unroll
    for (int off = 8; off; off >>= 1)
        m = fmaxf(m, __shfl_xor_sync(0xffffffffu, m, off));
    float sum = 0.f;
#pragma unroll
    for (int i = 0; i < 32; i++) { sreg[i] = expf(sreg[i] - m); sum += sreg[i]; }
#pragma unroll
    for (int off = 8; off; off >>= 1)
        sum += __shfl_xor_sync(0xffffffffu, sum, off);
    float inv = 1.f / sum;

    float* arow = g_att + ((size_t)z * TSEQ + q0 + rr) * TSEQ;
#pragma unroll
    for (int kt = 0; kt < 16; kt++) {
        arow[kt * 32 + j]      = sreg[2 * kt] * inv;
        arow[kt * 32 + 16 + j] = sreg[2 * kt + 1] * inv;
    }
}

// ============================================================================
// AV GEMM (NN, strided) — SIMT; writes bf16 hi/lo
// ============================================================================
__global__ void __launch_bounds__(256) gemm_av()
{
    int z = blockIdx.z;
    int b = z >> 3, h = z & 7;
    const float* A  = g_att + (size_t)z * TSEQ * TSEQ;
    const float* Bb = g_qkv + (size_t)b * TSEQ * (3 * DMODEL) + 2 * DMODEL + h * HD;
    size_t cbase = (size_t)b * TSEQ * DMODEL + h * HD;

    __shared__ float As[16][128];
    __shared__ float Bs[16][64];
    int t  = threadIdx.x;
    int m0 = blockIdx.y * 128;
    int n0 = blockIdx.x * 64;
    int tx = t & 15, ty = t >> 4;

    float acc[8][4];
#pragma unroll
    for (int i = 0; i < 8; i++)
#pragma unroll
        for (int j = 0; j < 4; j++) acc[i][j] = 0.f;

    for (int k0 = 0; k0 < TSEQ; k0 += 16) {
#pragma unroll
        for (int s = 0; s < 2; s++) {
            int v = t + s * 256;
            int row = v >> 2, c4 = (v & 3) * 4;
            float4 a = *(const float4*)(A + (size_t)(m0 + row) * TSEQ + k0 + c4);
            As[c4 + 0][row] = a.x; As[c4 + 1][row] = a.y;
            As[c4 + 2][row] = a.z; As[c4 + 3][row] = a.w;
        }
        {
            int kr = t >> 4, c4 = (t & 15) * 4;
            float4 bv = *(const float4*)(Bb + (size_t)(k0 + kr) * (3 * DMODEL) + n0 + c4);
            *(float4*)&Bs[kr][c4] = bv;
        }
        __syncthreads();
#pragma unroll
        for (int kk = 0; kk < 16; kk++) {
            float ar[8], br[4];
#pragma unroll
            for (int i = 0; i < 8; i++) ar[i] = As[kk][ty * 8 + i];
#pragma unroll
            for (int jj = 0; jj < 4; jj++) br[jj] = Bs[kk][tx * 4 + jj];
#pragma unroll
            for (int i = 0; i < 8; i++)
#pragma unroll
                for (int jj = 0; jj < 4; jj++) acc[i][jj] += ar[i] * br[jj];
        }
        __syncthreads();
    }
#pragma unroll
    for (int i = 0; i < 8; i++) {
        int m = m0 + ty * 8 + i;
#pragma unroll
        for (int jj = 0; jj < 4; jj++) {
            float v = acc[i][jj];
            size_t idx = cbase + (size_t)m * DMODEL + n0 + tx * 4 + jj;
            __nv_bfloat16 hh = __float2bfloat16(v);
            g_ao_hi[idx] = hh;
            g_ao_lo[idx] = __float2bfloat16(v - __bfloat162float(hh));
        }
    }
}

// mean over heads for attn_weights output
__global__ void __launch_bounds__(256) attn_mean(float* __restrict__ out)
{
    int idx = blockIdx.x * 256 + threadIdx.x;
    int b   = idx / (TSEQ * TSEQ);
    int rem = idx - b * (TSEQ * TSEQ);
    float s = 0.f;
#pragma unroll
    for (int h = 0; h < 8; h++)
        s += g_att[((size_t)(b * 8 + h)) * (TSEQ * TSEQ) + rem];
    out[idx] = s * 0.125f;
}

// final: y = rmsnorm(x + peer_proj + ao_proj) * rms_w
__global__ void __launch_bounds__(256) final_rms(
    const float* __restrict__ x, const float* __restrict__ rms_w,
    float* __restrict__ y)
{
    int token = blockIdx.x;
    int t = threadIdx.x;
    size_t base = (size_t)token * DMODEL;
    float v[4];
    float ss = 0.f;
#pragma unroll
    for (int u = 0; u < 4; u++) {
        int c = t + u * 256;
        float s = x[base + c] + g_peer_proj[base + c] + g_ao_proj[base + c];
        v[u] = s;
        ss += s * s;
    }
#pragma unroll
    for (int off = 16; off; off >>= 1)
        ss += __shfl_xor_sync(0xffffffffu, ss, off);
    __shared__ float red[8];
    __shared__ float stot;
    if ((t & 31) == 0) red[t >> 5] = ss;
    __syncthreads();
    if (t == 0) {
        float s = 0.f;
#pragma unroll
        for (int i = 0; i < 8; i++) s += red[i];
        stot = rsqrtf(s * (1.f / DMODEL) + 1e-6f);
    }
    __syncthreads();
    float inv = stot;
#pragma unroll
    for (int u = 0; u < 4; u++) {
        int c = t + u * 256;
        y[base + c] = v[u] * inv * rms_w[c];
    }
}

// ============================================================================
extern "C" void kernel_launch(void* const* d_in, const int* in_sizes, int n_in,
                              void* d_out, int out_size)
{
    const float* x         = (const float*)d_in[0];
    const float* wq        = (const float*)d_in[1];
    const float* bq        = (const float*)d_in[2];
    const float* bn_w      = (const float*)d_in[3];
    const float* bn_b      = (const float*)d_in[4];
    const float* bn_mean   = (const float*)d_in[5];
    const float* bn_var    = (const float*)d_in[6];
    const float* sub_keys  = (const float*)d_in[7];
    const float* expert_w  = (const float*)d_in[8];
    const float* wo        = (const float*)d_in[9];
    const float* bo        = (const float*)d_in[10];
    const float* in_proj_w = (const float*)d_in[11];
    const float* in_proj_b = (const float*)d_in[12];
    const float* attn_ow   = (const float*)d_in[13];
    const float* attn_ob   = (const float*)d_in[14];
    const float* rms_w     = (const float*)d_in[15];

    float* y      = (float*)d_out;                         // (2,512,1024)
    float* attn_w = (float*)d_out + (size_t)NTOK * DMODEL; // (2,512,512)

    void *p_q, *p_qkv, *p_pp, *p_ap;
    cudaGetSymbolAddress(&p_q, g_q);
    cudaGetSymbolAddress(&p_qkv, g_qkv);
    cudaGetSymbolAddress(&p_pp, g_peer_proj);
    cudaGetSymbolAddress(&p_ap, g_ao_proj);

    void *xh, *xl, *wqh, *wql, *iph, *ipl, *woh, *wol, *awh, *awl, *ph, *pl, *aoh, *aol;
    cudaGetSymbolAddress(&xh,  g_x_hi);  cudaGetSymbolAddress(&xl,  g_x_lo);
    cudaGetSymbolAddress(&wqh, g_wq_hi); cudaGetSymbolAddress(&wql, g_wq_lo);
    cudaGetSymbolAddress(&iph, g_ip_hi); cudaGetSymbolAddress(&ipl, g_ip_lo);
    cudaGetSymbolAddress(&woh, g_wo_hi); cudaGetSymbolAddress(&wol, g_wo_lo);
    cudaGetSymbolAddress(&awh, g_aow_hi); cudaGetSymbolAddress(&awl, g_aow_lo);
    cudaGetSymbolAddress(&ph,  g_peer_hi); cudaGetSymbolAddress(&pl,  g_peer_lo);
    cudaGetSymbolAddress(&aoh, g_ao_hi); cudaGetSymbolAddress(&aol, g_ao_lo);

    cudaFuncSetAttribute(gemm_bf16, cudaFuncAttributeMaxDynamicSharedMemorySize,
                         GEMM_SMEM);

    // ---- pre-split fp32 -> bf16 hi/lo ----
    split_bf16<<<(NTOK * DMODEL) / 1024, 256>>>(x, (__nv_bfloat16*)xh, (__nv_bfloat16*)xl);
    split_bf16<<<(DMODEL * DMODEL) / 1024, 256>>>(wq, (__nv_bfloat16*)wqh, (__nv_bfloat16*)wql);
    split_bf16<<<(3 * DMODEL * DMODEL) / 1024, 256>>>(in_proj_w, (__nv_bfloat16*)iph, (__nv_bfloat16*)ipl);
    split_bf16<<<(DMODEL * DMODEL) / 1024, 256>>>(wo, (__nv_bfloat16*)woh, (__nv_bfloat16*)wol);
    split_bf16<<<(DMODEL * DMODEL) / 1024, 256>>>(attn_ow, (__nv_bfloat16*)awh, (__nv_bfloat16*)awl);

    // ---- q = x @ wq^T + bq ----
    gemm_bf16<<<dim3(DMODEL / 128, NTOK / 64), 256, GEMM_SMEM>>>(
        (const __nv_bfloat16*)xh, (const __nv_bfloat16*)xl,
        (const __nv_bfloat16*)wqh, (const __nv_bfloat16*)wql,
        bq, (float*)p_q, NTOK, DMODEL, DMODEL);

    // ---- qkv = x @ in_proj^T + b ----
    gemm_bf16<<<dim3(3 * DMODEL / 128, NTOK / 64), 256, GEMM_SMEM>>>(
        (const __nv_bfloat16*)xh, (const __nv_bfloat16*)xl,
        (const __nv_bfloat16*)iph, (const __nv_bfloat16*)ipl,
        in_proj_b, (float*)p_qkv, NTOK, 3 * DMODEL, DMODEL);

    // ---- PEER routing + expert mixture ----
    peer_route<<<NTOK * NHEADS, 128>>>(bn_w, bn_b, bn_mean, bn_var, sub_keys, expert_w);

    // ---- attention ----
    attn_scores<<<dim3(TSEQ / 16, BATCH * NHEADS), 256>>>();
    gemm_av<<<dim3(HD / 64, TSEQ / 128, BATCH * NHEADS), 256>>>();
    attn_mean<<<(BATCH * TSEQ * TSEQ) / 256, 256>>>(attn_w);

    // ---- output projections ----
    gemm_bf16<<<dim3(DMODEL / 128, NTOK / 64), 256, GEMM_SMEM>>>(
        (const __nv_bfloat16*)ph, (const __nv_bfloat16*)pl,
        (const __nv_bfloat16*)woh, (const __nv_bfloat16*)wol,
        bo, (float*)p_pp, NTOK, DMODEL, DMODEL);
    gemm_bf16<<<dim3(DMODEL / 128, NTOK / 64), 256, GEMM_SMEM>>>(
        (const __nv_bfloat16*)aoh, (const __nv_bfloat16*)aol,
        (const __nv_bfloat16*)awh, (const __nv_bfloat16*)awl,
        attn_ob, (float*)p_ap, NTOK, DMODEL, DMODEL);

    // ---- residual + rmsnorm ----
    final_rms<<<NTOK, 256>>>(x, rms_w, y);

    (void)in_sizes; (void)n_in; (void)out_size;
}

// round 5
// speedup vs baseline: 1.3254x; 1.0645x over previous
#include <cuda_runtime.h>
#include <cuda_bf16.h>
#include <math.h>
#include <stdint.h>

// ---------------- problem constants ----------------
#define BATCH   2
#define TSEQ    512
#define NTOK    1024
#define DMODEL  1024
#define NHEADS  8
#define DKEY    128
#define HK      1024
#define NSUB    128
#define TOPK    16
#define HD      128

// ---------------- scratch ----------------
__device__ __align__(128) float g_q[NTOK * HK];
__device__ __align__(128) float g_qkv[NTOK * 3 * DMODEL];
__device__ __align__(128) float g_att[BATCH * NHEADS * TSEQ * TSEQ];   // 16 MB
__device__ __align__(128) float g_sum[NTOK * DMODEL];

__device__ __align__(128) __nv_bfloat16 g_x_hi[NTOK * DMODEL],  g_x_lo[NTOK * DMODEL];
__device__ __align__(128) __nv_bfloat16 g_w1_hi[4096 * DMODEL], g_w1_lo[4096 * DMODEL]; // [wq;in_proj]
__device__ __align__(128) __nv_bfloat16 g_w2_hi[DMODEL * 2048], g_w2_lo[DMODEL * 2048]; // [wo|attn_ow]
__device__ __align__(128) __nv_bfloat16 g_cat_hi[NTOK * 2048],  g_cat_lo[NTOK * 2048];  // [peer|ao]
__device__ __align__(128) float g_bias1[4096];
__device__ __align__(128) float g_bias2[DMODEL];

// ---------------- helpers ----------------
__device__ __forceinline__ uint32_t smem_u32(const void* p) {
    uint32_t a;
    asm("{ .reg .u64 t; cvta.to.shared.u64 t, %1; cvt.u32.u64 %0, t; }"
        : "=r"(a) : "l"(p));
    return a;
}
#define LDSM4(r, addr) \
    asm volatile("ldmatrix.sync.aligned.m8n8.x4.shared.b16 {%0,%1,%2,%3}, [%4];" \
        : "=r"((r)[0]), "=r"((r)[1]), "=r"((r)[2]), "=r"((r)[3]) : "r"(addr))
#define MMA_BF16(d, a, b0, b1) \
    asm volatile("mma.sync.aligned.m16n8k16.row.col.f32.bf16.bf16.f32 " \
        "{%0,%1,%2,%3}, {%4,%5,%6,%7}, {%8,%9}, {%0,%1,%2,%3};" \
        : "+f"((d)[0]), "+f"((d)[1]), "+f"((d)[2]), "+f"((d)[3]) \
        : "r"((a)[0]), "r"((a)[1]), "r"((a)[2]), "r"((a)[3]), "r"(b0), "r"(b1))
#define CP16(dst, src) \
    asm volatile("cp.async.cg.shared.global [%0], [%1], 16;" :: "r"(dst), "l"(src))
#define CP_COMMIT() asm volatile("cp.async.commit_group;" ::: "memory")
#define CP_WAIT1()  asm volatile("cp.async.wait_group 1;" ::: "memory")

// ============================================================================
// split kernels (fp32 -> bf16 hi/lo)
// ============================================================================
__device__ __forceinline__ void split_store4(float4 v, __nv_bfloat16* hi,
                                             __nv_bfloat16* lo, size_t i4) {
    float vv[4] = {v.x, v.y, v.z, v.w};
    __nv_bfloat16 h[4], l[4];
#pragma unroll
    for (int k = 0; k < 4; k++) {
        h[k] = __float2bfloat16(vv[k]);
        l[k] = __float2bfloat16(vv[k] - __bfloat162float(h[k]));
    }
    ((__nv_bfloat162*)hi)[2 * i4]     = __nv_bfloat162(h[0], h[1]);
    ((__nv_bfloat162*)hi)[2 * i4 + 1] = __nv_bfloat162(h[2], h[3]);
    ((__nv_bfloat162*)lo)[2 * i4]     = __nv_bfloat162(l[0], l[1]);
    ((__nv_bfloat162*)lo)[2 * i4 + 1] = __nv_bfloat162(l[2], l[3]);
}

__global__ void __launch_bounds__(256) split_x(const float* __restrict__ src) {
    size_t i = (size_t)blockIdx.x * 256 + threadIdx.x;
    split_store4(((const float4*)src)[i], g_x_hi, g_x_lo, i);
}
// [wq (1024 rows) ; in_proj (3072 rows)] -> g_w1 (4096 x 1024)
__global__ void __launch_bounds__(256) split_w1(const float* __restrict__ wq,
                                                const float* __restrict__ ipw) {
    size_t i = (size_t)blockIdx.x * 256 + threadIdx.x;     // float4 index
    const size_t cut = (size_t)1024 * 1024 / 4;
    float4 v = (i < cut) ? ((const float4*)wq)[i] : ((const float4*)ipw)[i - cut];
    split_store4(v, g_w1_hi, g_w1_lo, i);
}
// [wo | attn_ow] row-interleaved -> g_w2 (1024 x 2048)
__global__ void __launch_bounds__(256) split_w2(const float* __restrict__ wo,
                                                const float* __restrict__ aow) {
    size_t i = (size_t)blockIdx.x * 256 + threadIdx.x;     // float4 index over 1024x2048
    int row = (int)(i >> 9);          // 512 float4 per row
    int c4  = (int)(i & 511);
    float4 v = (c4 < 256) ? ((const float4*)wo)[row * 256 + c4]
                          : ((const float4*)aow)[row * 256 + c4 - 256];
    split_store4(v, g_w2_hi, g_w2_lo, i);
}
__global__ void __launch_bounds__(256) bias_cat1(const float* __restrict__ bq,
                                                 const float* __restrict__ ipb) {
    int i = blockIdx.x * 256 + threadIdx.x;
    g_bias1[i] = (i < 1024) ? bq[i] : ipb[i - 1024];
}
__global__ void __launch_bounds__(256) bias_cat2(const float* __restrict__ bo,
                                                 const float* __restrict__ aob) {
    int i = blockIdx.x * 256 + threadIdx.x;
    g_bias2[i] = bo[i] + aob[i];
}

// ============================================================================
// bf16-split "3M" GEMM, templated on NT (warp n-tiles): BN = NT*32
// C[M,N] = A[M,K] @ B[N,K]^T + bias ; output split at ncut between C0/C1.
// 3-stage cp.async pipeline, ONE __syncthreads per K-iteration.
// ============================================================================
template<int NT>
__global__ void __launch_bounds__(256) gemm_fused(
    const __nv_bfloat16* __restrict__ Ahi, const __nv_bfloat16* __restrict__ Alo,
    const __nv_bfloat16* __restrict__ Bhi, const __nv_bfloat16* __restrict__ Blo,
    const float* __restrict__ bias,
    float* __restrict__ C0, int ld0, float* __restrict__ C1, int ld1, int ncut,
    int K)
{
    constexpr int BN = NT * 32;
    constexpr int A_T = 64 * 80;          // bytes per A hi (or lo) tile
    constexpr int B_T = BN * 80;
    constexpr int STAGE = 2 * A_T + 2 * B_T;

    extern __shared__ char smc[];
    uint32_t base = smem_u32(smc);
    int t = threadIdx.x, warp = t >> 5, lane = t & 31;
    int m0 = blockIdx.y * 64, n0 = blockIdx.x * BN;
    int wm = warp >> 2, wn = warp & 3;

    float acc[2][NT][4];
#pragma unroll
    for (int i = 0; i < 2; i++)
#pragma unroll
        for (int j = 0; j < NT; j++)
#pragma unroll
            for (int r = 0; r < 4; r++) acc[i][j][r] = 0.f;

    const int niter = K >> 5;

    auto issue = [&](int it) {
        uint32_t sb = base + (it % 3) * STAGE;
        int k0 = it << 5;
        {   // A: 64 rows x 4 chunks
            int row = t >> 2, j = t & 3;
            const __nv_bfloat16* sh = Ahi + (size_t)(m0 + row) * K + k0 + j * 8;
            const __nv_bfloat16* sl = Alo + (size_t)(m0 + row) * K + k0 + j * 8;
            uint32_t d = sb + (uint32_t)(row * 80 + j * 16);
            CP16(d, sh);
            CP16(d + A_T, sl);
        }
#pragma unroll
        for (int p = 0; p < BN / 64; p++) {  // B: BN rows x 4 chunks
            int c = t + p * 256;
            int row = c >> 2, j = c & 3;
            const __nv_bfloat16* sh = Bhi + (size_t)(n0 + row) * K + k0 + j * 8;
            const __nv_bfloat16* sl = Blo + (size_t)(n0 + row) * K + k0 + j * 8;
            uint32_t d = sb + 2 * A_T + (uint32_t)(row * 80 + j * 16);
            CP16(d, sh);
            CP16(d + B_T, sl);
        }
    };

    issue(0); CP_COMMIT();
    issue(1); CP_COMMIT();

    uint32_t a_off = (uint32_t)((wm * 32 + (lane & 15)) * 80 + (lane >> 4) * 16);
    uint32_t b_off = (uint32_t)((wn * (NT * 8) + (lane & 15)) * 80 + (lane >> 4) * 16);

    for (int it = 0; it < niter; ++it) {
        CP_WAIT1();
        __syncthreads();                     // single barrier per iteration
        if (it + 2 < niter) issue(it + 2);   // writes stage (it-1)%3: all warps past it-1
        CP_COMMIT();

        uint32_t sb = base + (it % 3) * STAGE;
        uint32_t sa_h = sb, sa_l = sb + A_T;
        uint32_t sb_h = sb + 2 * A_T, sb_l = sb_h + B_T;

#pragma unroll
        for (int ks = 0; ks < 2; ks++) {
            uint32_t kb = ks * 32;
            uint32_t ah[2][4], al[2][4], bh[NT / 2 + (NT == 2)][4], bl[NT / 2 + (NT == 2)][4];
            constexpr int BT = (NT == 4) ? 2 : 1;
#pragma unroll
            for (int mt = 0; mt < 2; mt++) {
                uint32_t o = a_off + mt * 16 * 80 + kb;
                LDSM4(ah[mt], sa_h + o);
                LDSM4(al[mt], sa_l + o);
            }
#pragma unroll
            for (int bt = 0; bt < BT; bt++) {
                uint32_t o = b_off + bt * 16 * 80 + kb;
                LDSM4(bh[bt], sb_h + o);
                LDSM4(bl[bt], sb_l + o);
            }
#pragma unroll
            for (int mt = 0; mt < 2; mt++) {
#pragma unroll
                for (int nt = 0; nt < NT; nt++) {
                    int bt = nt >> 1, s2 = nt & 1;
                    MMA_BF16(acc[mt][nt], ah[mt], bh[bt][s2], bh[bt][s2 + 2]);
                    MMA_BF16(acc[mt][nt], al[mt], bh[bt][s2], bh[bt][s2 + 2]);
                    MMA_BF16(acc[mt][nt], ah[mt], bl[bt][s2], bl[bt][s2 + 2]);
                }
            }
        }
        __syncthreads();  // protect stage reuse before next wait advances
    }

    // ---- epilogue ----
    int g = lane >> 2, c2 = lane & 3;
#pragma unroll
    for (int mt = 0; mt < 2; mt++) {
#pragma unroll
        for (int nt = 0; nt < NT; nt++) {
            int row = m0 + wm * 32 + mt * 16 + g;
            int col = n0 + wn * (NT * 8) + nt * 8 + 2 * c2;
            float b0 = bias[col], b1 = bias[col + 1];
            float* C; int ld, cc;
            if (col < ncut) { C = C0; ld = ld0; cc = col; }
            else            { C = C1; ld = ld1; cc = col - ncut; }
            *(float2*)(C + (size_t)row * ld + cc) =
                make_float2(acc[mt][nt][0] + b0, acc[mt][nt][1] + b1);
            *(float2*)(C + (size_t)(row + 8) * ld + cc) =
                make_float2(acc[mt][nt][2] + b0, acc[mt][nt][3] + b1);
        }
    }
}

// ============================================================================
// PEER routing -> writes bf16 hi/lo into cat cols [0,1024)
// ============================================================================
__global__ void __launch_bounds__(128) peer_route(
    const float* __restrict__ bn_w, const float* __restrict__ bn_b,
    const float* __restrict__ bn_mean, const float* __restrict__ bn_var,
    const float* __restrict__ sub_keys, const float* __restrict__ expert_w)
{
    int token = blockIdx.x >> 3;
    int head  = blockIdx.x & 7;
    int tid   = threadIdx.x;

    __shared__ float q[128];
    __shared__ float s1[128], s2[128];
    __shared__ float v1[16], v2[16];
    __shared__ int   i1[16], i2[16];
    __shared__ float cval[256];
    __shared__ int   cidx[256];
    __shared__ int   sel[16];
    __shared__ float simv[16];
    __shared__ float rw[16];
    __shared__ float ews[16][128];

    int c = head * 128 + tid;
    float qraw = g_q[(size_t)token * HK + c];
    float qb = (qraw - bn_mean[c]) * rsqrtf(bn_var[c] + 1e-5f) * bn_w[c] + bn_b[c];
    q[tid] = qb;
    __syncthreads();

    float a1 = 0.f, a2 = 0.f;
    const float* k1p = sub_keys + (size_t)tid * 64;
    const float* k2p = sub_keys + (size_t)NSUB * 64 + (size_t)tid * 64;
#pragma unroll 8
    for (int i = 0; i < 64; i++) {
        a1 += q[i]      * k1p[i];
        a2 += q[64 + i] * k2p[i];
    }
    s1[tid] = a1; s2[tid] = a2;
    __syncthreads();

    int r1 = 0, r2 = 0;
    for (int j = 0; j < 128; j++) {
        float x1 = s1[j]; r1 += (x1 > a1) || (x1 == a1 && j < tid);
        float x2 = s2[j]; r2 += (x2 > a2) || (x2 == a2 && j < tid);
    }
    if (r1 < 16) { v1[r1] = a1; i1[r1] = tid; }
    if (r2 < 16) { v2[r2] = a2; i2[r2] = tid; }
    __syncthreads();

    for (int p = tid; p < 256; p += 128) {
        int a = p >> 4, bb = p & 15;
        cval[p] = v1[a] + v2[bb];
        cidx[p] = i1[a] * NSUB + i2[bb];
    }
    __syncthreads();
    for (int p = tid; p < 256; p += 128) {
        float v = cval[p];
        int r = 0;
        for (int j = 0; j < 256; j++) {
            float w = cval[j];
            r += (w > v) || (w == v && j < p);
        }
        if (r < 16) sel[r] = cidx[p];
    }
    __syncthreads();

#pragma unroll
    for (int k = 0; k < 16; k++)
        ews[k][tid] = expert_w[(size_t)sel[k] * DKEY + tid];
    __syncthreads();

    int k8 = tid >> 3, l8 = tid & 7;
    float part = 0.f;
#pragma unroll
    for (int i = 0; i < 16; i++) {
        int d = l8 * 16 + i;
        part += q[d] * ews[k8][d];
    }
    part += __shfl_down_sync(0xffffffffu, part, 4);
    part += __shfl_down_sync(0xffffffffu, part, 2);
    part += __shfl_down_sync(0xffffffffu, part, 1);
    if (l8 == 0) simv[k8] = part;
    __syncthreads();

    if (tid == 0) {
        float m = -INFINITY;
#pragma unroll
        for (int k = 0; k < 16; k++) m = fmaxf(m, simv[k]);
        float e[16]; float s = 0.f;
#pragma unroll
        for (int k = 0; k < 16; k++) { e[k] = expf(simv[k] - m); s += e[k]; }
        float inv = 1.f / s;
#pragma unroll
        for (int k = 0; k < 16; k++) rw[k] = e[k] * inv;
    }
    __syncthreads();

    float o = 0.f;
#pragma unroll
    for (int k = 0; k < 16; k++) o += rw[k] * ews[k][tid];
    size_t idx = (size_t)token * 2048 + c;
    __nv_bfloat16 h = __float2bfloat16(o);
    g_cat_hi[idx] = h;
    g_cat_lo[idx] = __float2bfloat16(o - __bfloat162float(h));
}

// ============================================================================
// Attention scores + softmax
// ============================================================================
__global__ void __launch_bounds__(256) attn_scores()
{
    int z = blockIdx.y;
    int b = z >> 3, h = z & 7;
    int q0 = blockIdx.x * 16;
    int t = threadIdx.x;

    __shared__ float qs[16][128];
    __shared__ float Ks[32][132];

#pragma unroll
    for (int s = 0; s < 2; s++) {
        int v = t + s * 256;
        int r = v >> 5, c4 = (v & 31) * 4;
        float4 val = *(const float4*)&g_qkv[(size_t)(b * TSEQ + q0 + r) * (3 * DMODEL) + h * HD + c4];
        *(float4*)&qs[r][c4] = val;
    }
    __syncthreads();

    int j  = t & 15;
    int rr = t >> 4;
    float sreg[32];

    for (int kt = 0; kt < 16; kt++) {
#pragma unroll
        for (int s = 0; s < 4; s++) {
            int v = t + s * 256;
            int kr = v >> 5, c4 = (v & 31) * 4;
            float4 val = *(const float4*)&g_qkv[(size_t)(b * TSEQ + kt * 32 + kr) * (3 * DMODEL) + DMODEL + h * HD + c4];
            Ks[kr][c4 + 0] = val.x; Ks[kr][c4 + 1] = val.y;
            Ks[kr][c4 + 2] = val.z; Ks[kr][c4 + 3] = val.w;
        }
        __syncthreads();
        float acc1 = 0.f, acc2 = 0.f;
        const float4* qr  = (const float4*)&qs[rr][0];
        const float4* ka4 = (const float4*)&Ks[j][0];
        const float4* kb4 = (const float4*)&Ks[j + 16][0];
#pragma unroll
        for (int i = 0; i < 32; i++) {
            float4 qv = qr[i];
            float4 a  = ka4[i];
            float4 bb = kb4[i];
            acc1 += qv.x * a.x + qv.y * a.y + qv.z * a.z + qv.w * a.w;
            acc2 += qv.x * bb.x + qv.y * bb.y + qv.z * bb.z + qv.w * bb.w;
        }
        sreg[2 * kt]     = acc1;
        sreg[2 * kt + 1] = acc2;
        __syncthreads();
    }

    const float scale = 0.08838834764831845f;
#pragma unroll
    for (int i = 0; i < 32; i++) sreg[i] *= scale;

    float m = -INFINITY;
#pragma unroll
    for (int i = 0; i < 32; i++) m = fmaxf(m, sreg[i]);
#pragma unroll
    for (int off = 8; off; off >>= 1)
        m = fmaxf(m, __shfl_xor_sync(0xffffffffu, m, off));
    float sum = 0.f;
#pragma unroll
    for (int i = 0; i < 32; i++) { sreg[i] = expf(sreg[i] - m); sum += sreg[i]; }
#pragma unroll
    for (int off = 8; off; off >>= 1)
        sum += __shfl_xor_sync(0xffffffffu, sum, off);
    float inv = 1.f / sum;

    float* arow = g_att + ((size_t)z * TSEQ + q0 + rr) * TSEQ;
#pragma unroll
    for (int kt = 0; kt < 16; kt++) {
        arow[kt * 32 + j]      = sreg[2 * kt] * inv;
        arow[kt * 32 + 16 + j] = sreg[2 * kt + 1] * inv;
    }
}

// ============================================================================
// AV GEMM (SIMT) -> writes bf16 hi/lo into cat cols [1024,2048)
// ============================================================================
__global__ void __launch_bounds__(256) gemm_av()
{
    int z = blockIdx.z;
    int b = z >> 3, h = z & 7;
    const float* A  = g_att + (size_t)z * TSEQ * TSEQ;
    const float* Bb = g_qkv + (size_t)b * TSEQ * (3 * DMODEL) + 2 * DMODEL + h * HD;

    __shared__ float As[16][128];
    __shared__ float Bs[16][64];
    int t  = threadIdx.x;
    int m0 = blockIdx.y * 128;
    int n0 = blockIdx.x * 64;
    int tx = t & 15, ty = t >> 4;

    float acc[8][4];
#pragma unroll
    for (int i = 0; i < 8; i++)
#pragma unroll
        for (int j = 0; j < 4; j++) acc[i][j] = 0.f;

    for (int k0 = 0; k0 < TSEQ; k0 += 16) {
#pragma unroll
        for (int s = 0; s < 2; s++) {
            int v = t + s * 256;
            int row = v >> 2, c4 = (v & 3) * 4;
            float4 a = *(const float4*)(A + (size_t)(m0 + row) * TSEQ + k0 + c4);
            As[c4 + 0][row] = a.x; As[c4 + 1][row] = a.y;
            As[c4 + 2][row] = a.z; As[c4 + 3][row] = a.w;
        }
        {
            int kr = t >> 4, c4 = (t & 15) * 4;
            float4 bv = *(const float4*)(Bb + (size_t)(k0 + kr) * (3 * DMODEL) + n0 + c4);
            *(float4*)&Bs[kr][c4] = bv;
        }
        __syncthreads();
#pragma unroll
        for (int kk = 0; kk < 16; kk++) {
            float ar[8], br[4];
#pragma unroll
            for (int i = 0; i < 8; i++) ar[i] = As[kk][ty * 8 + i];
#pragma unroll
            for (int jj = 0; jj < 4; jj++) br[jj] = Bs[kk][tx * 4 + jj];
#pragma unroll
            for (int i = 0; i < 8; i++)
#pragma unroll
                for (int jj = 0; jj < 4; jj++) acc[i][jj] += ar[i] * br[jj];
        }
        __syncthreads();
    }
#pragma unroll
    for (int i = 0; i < 8; i++) {
        int m = m0 + ty * 8 + i;        // token within batch b
        int token = b * TSEQ + m;
#pragma unroll
        for (int jj = 0; jj < 4; jj++) {
            float v = acc[i][jj];
            size_t idx = (size_t)token * 2048 + 1024 + h * HD + n0 + tx * 4 + jj;
            __nv_bfloat16 hh = __float2bfloat16(v);
            g_cat_hi[idx] = hh;
            g_cat_lo[idx] = __float2bfloat16(v - __bfloat162float(hh));
        }
    }
}

// mean over heads
__global__ void __launch_bounds__(256) attn_mean(float* __restrict__ out)
{
    int idx = blockIdx.x * 256 + threadIdx.x;
    int b   = idx / (TSEQ * TSEQ);
    int rem = idx - b * (TSEQ * TSEQ);
    float s = 0.f;
#pragma unroll
    for (int h = 0; h < 8; h++)
        s += g_att[((size_t)(b * 8 + h)) * (TSEQ * TSEQ) + rem];
    out[idx] = s * 0.125f;
}

// y = rmsnorm(x + g_sum) * rms_w
__global__ void __launch_bounds__(256) final_rms(
    const float* __restrict__ x, const float* __restrict__ rms_w,
    float* __restrict__ y)
{
    int token = blockIdx.x;
    int t = threadIdx.x;
    size_t base = (size_t)token * DMODEL;
    float v[4];
    float ss = 0.f;
#pragma unroll
    for (int u = 0; u < 4; u++) {
        int c = t + u * 256;
        float s = x[base + c] + g_sum[base + c];
        v[u] = s;
        ss += s * s;
    }
#pragma unroll
    for (int off = 16; off; off >>= 1)
        ss += __shfl_xor_sync(0xffffffffu, ss, off);
    __shared__ float red[8];
    __shared__ float stot;
    if ((t & 31) == 0) red[t >> 5] = ss;
    __syncthreads();
    if (t == 0) {
        float s = 0.f;
#pragma unroll
        for (int i = 0; i < 8; i++) s += red[i];
        stot = rsqrtf(s * (1.f / DMODEL) + 1e-6f);
    }
    __syncthreads();
    float inv = stot;
#pragma unroll
    for (int u = 0; u < 4; u++) {
        int c = t + u * 256;
        y[base + c] = v[u] * inv * rms_w[c];
    }
}

// ============================================================================
extern "C" void kernel_launch(void* const* d_in, const int* in_sizes, int n_in,
                              void* d_out, int out_size)
{
    const float* x         = (const float*)d_in[0];
    const float* wq        = (const float*)d_in[1];
    const float* bq        = (const float*)d_in[2];
    const float* bn_w      = (const float*)d_in[3];
    const float* bn_b      = (const float*)d_in[4];
    const float* bn_mean   = (const float*)d_in[5];
    const float* bn_var    = (const float*)d_in[6];
    const float* sub_keys  = (const float*)d_in[7];
    const float* expert_w  = (const float*)d_in[8];
    const float* wo        = (const float*)d_in[9];
    const float* bo        = (const float*)d_in[10];
    const float* in_proj_w = (const float*)d_in[11];
    const float* in_proj_b = (const float*)d_in[12];
    const float* attn_ow   = (const float*)d_in[13];
    const float* attn_ob   = (const float*)d_in[14];
    const float* rms_w     = (const float*)d_in[15];

    float* y      = (float*)d_out;
    float* attn_w = (float*)d_out + (size_t)NTOK * DMODEL;

    void *p_q, *p_qkv, *p_sum;
    cudaGetSymbolAddress(&p_q, g_q);
    cudaGetSymbolAddress(&p_qkv, g_qkv);
    cudaGetSymbolAddress(&p_sum, g_sum);

    void *xh, *xl, *w1h, *w1l, *w2h, *w2l, *ch, *cl, *b1, *b2;
    cudaGetSymbolAddress(&xh,  g_x_hi);  cudaGetSymbolAddress(&xl,  g_x_lo);
    cudaGetSymbolAddress(&w1h, g_w1_hi); cudaGetSymbolAddress(&w1l, g_w1_lo);
    cudaGetSymbolAddress(&w2h, g_w2_hi); cudaGetSymbolAddress(&w2l, g_w2_lo);
    cudaGetSymbolAddress(&ch,  g_cat_hi); cudaGetSymbolAddress(&cl, g_cat_lo);
    cudaGetSymbolAddress(&b1,  g_bias1); cudaGetSymbolAddress(&b2, g_bias2);

    constexpr int SMEM4 = 3 * (2 * 64 * 80 + 2 * 128 * 80);  // 92160
    constexpr int SMEM2 = 3 * (2 * 64 * 80 + 2 * 64 * 80);   // 61440
    cudaFuncSetAttribute(gemm_fused<4>, cudaFuncAttributeMaxDynamicSharedMemorySize, SMEM4);
    cudaFuncSetAttribute(gemm_fused<2>, cudaFuncAttributeMaxDynamicSharedMemorySize, SMEM2);

    // [0..4] splits + biases (gemm1 = launch index 5 for ncu capture)
    split_x <<<(NTOK * DMODEL) / 1024, 256>>>(x);
    split_w1<<<(4096 * DMODEL) / 1024, 256>>>(wq, in_proj_w);
    split_w2<<<(DMODEL * 2048) / 1024, 256>>>(wo, attn_ow);
    bias_cat1<<<16, 256>>>(bq, in_proj_b);
    bias_cat2<<<4, 256>>>(bo, attn_ob);

    // [5] fused q+qkv: x(1024x1024) @ w1(4096x1024)^T -> q | qkv
    gemm_fused<4><<<dim3(4096 / 128, NTOK / 64), 256, SMEM4>>>(
        (const __nv_bfloat16*)xh, (const __nv_bfloat16*)xl,
        (const __nv_bfloat16*)w1h, (const __nv_bfloat16*)w1l,
        (const float*)b1,
        (float*)p_q, HK, (float*)p_qkv, 3 * DMODEL, 1024, DMODEL);

    // PEER routing
    peer_route<<<NTOK * NHEADS, 128>>>(bn_w, bn_b, bn_mean, bn_var, sub_keys, expert_w);

    // attention
    attn_scores<<<dim3(TSEQ / 16, BATCH * NHEADS), 256>>>();
    gemm_av<<<dim3(HD / 64, TSEQ / 128, BATCH * NHEADS), 256>>>();
    attn_mean<<<(BATCH * TSEQ * TSEQ) / 256, 256>>>(attn_w);

    // fused output: cat(1024x2048) @ w2(1024x2048)^T -> g_sum (includes both biases)
    gemm_fused<2><<<dim3(DMODEL / 64, NTOK / 64), 256, SMEM2>>>(
        (const __nv_bfloat16*)ch, (const __nv_bfloat16*)cl,
        (const __nv_bfloat16*)w2h, (const __nv_bfloat16*)w2l,
        (const float*)b2,
        (float*)p_sum, DMODEL, (float*)p_sum, DMODEL, 1 << 30, 2048);

    // residual + rmsnorm
    final_rms<<<NTOK, 256>>>(x, rms_w, y);

    (void)in_sizes; (void)n_in; (void)out_size;
}